// round 9
// baseline (speedup 1.0000x reference)
#include <cuda_runtime.h>

// AdditiveEmission: local-window (w=3) additive attention, fused single kernel.
//   q = X@Wt, k = X@Wx
//   e[i,j] = Wa . tanh(q_i + k_j + bh) + ba,  j in {i-1,i,i+1} (clipped)
//   a = softmax_window(e) (+EPS), out_i = sum_j a[i,j] * x_j
//
// B=4, L=512, D=128.
// T=7 queries/tile, grid = 74 x 4 = 296 blocks = one wave at 2 CTAs/SM
// (8 warps/SMSP for latency cover). Block = 512 threads = 8 groups of 64;
// thread = channel pair (2j, 2j+1) so weights load as LDG.64.
//   Phase 1: 16 row-GEMVs (q0-6 via Wt, k0-8 via Wx), 2 rows per group,
//            each row computed exactly once. x rows broadcast from SMEM.
//   Phase 2: group t (<7) computes query t's 3 logits (tanh + 2-warp reduce).
//   Phase 3: windowed softmax (+EPS) + AV, STG.64 per thread.

#define B_     4
#define L_     512
#define D_     128
#define T_     7
#define TILES_ 74          // ceil(512/7)
#define XR_    9           // staged x rows: i0-1 .. i0+7
#define NQK_   (T_ + XR_)  // 16 result rows: 0..6 = q, 7..15 = k
#define EPS_   1e-8f

__device__ __forceinline__ float tanh_approx(float v) {
    float r;
    asm("tanh.approx.f32 %0, %1;" : "=f"(r) : "f"(v));
    return r;
}

// Two row-GEMVs for channel pair (2j,2j+1): row0 against W0, row1 against W1.
// SAME=true when W0==W1 (weight loads shared). x rows are group-broadcast LDS.
template<bool SAME>
__device__ __forceinline__ void gemv2(const float (*xs)[D_], float (*qk)[D_],
                                      const float* __restrict__ W0, int xsr0, int dst0,
                                      const float* __restrict__ W1, int xsr1, int dst1,
                                      int j)
{
    float2 acc0 = make_float2(0.f, 0.f);
    float2 acc1 = make_float2(0.f, 0.f);
    const float2* wp0 = reinterpret_cast<const float2*>(W0) + j;   // stride 64 per e
    const float2* wp1 = reinterpret_cast<const float2*>(W1) + j;

    #pragma unroll 2
    for (int e = 0; e < D_; e += 8) {
        float2 w0[8], w1[8];
        #pragma unroll
        for (int u = 0; u < 8; ++u) w0[u] = wp0[(e + u) * (D_ / 2)];
        if (!SAME) {
            #pragma unroll
            for (int u = 0; u < 8; ++u) w1[u] = wp1[(e + u) * (D_ / 2)];
        }
        const float4 a0 = *reinterpret_cast<const float4*>(&xs[xsr0][e]);
        const float4 a1 = *reinterpret_cast<const float4*>(&xs[xsr0][e + 4]);
        const float4 b0 = *reinterpret_cast<const float4*>(&xs[xsr1][e]);
        const float4 b1 = *reinterpret_cast<const float4*>(&xs[xsr1][e + 4]);

        acc0.x = fmaf(a0.x, w0[0].x, acc0.x); acc0.y = fmaf(a0.x, w0[0].y, acc0.y);
        acc0.x = fmaf(a0.y, w0[1].x, acc0.x); acc0.y = fmaf(a0.y, w0[1].y, acc0.y);
        acc0.x = fmaf(a0.z, w0[2].x, acc0.x); acc0.y = fmaf(a0.z, w0[2].y, acc0.y);
        acc0.x = fmaf(a0.w, w0[3].x, acc0.x); acc0.y = fmaf(a0.w, w0[3].y, acc0.y);
        acc0.x = fmaf(a1.x, w0[4].x, acc0.x); acc0.y = fmaf(a1.x, w0[4].y, acc0.y);
        acc0.x = fmaf(a1.y, w0[5].x, acc0.x); acc0.y = fmaf(a1.y, w0[5].y, acc0.y);
        acc0.x = fmaf(a1.z, w0[6].x, acc0.x); acc0.y = fmaf(a1.z, w0[6].y, acc0.y);
        acc0.x = fmaf(a1.w, w0[7].x, acc0.x); acc0.y = fmaf(a1.w, w0[7].y, acc0.y);

        const float2* wr = SAME ? w0 : w1;
        acc1.x = fmaf(b0.x, wr[0].x, acc1.x); acc1.y = fmaf(b0.x, wr[0].y, acc1.y);
        acc1.x = fmaf(b0.y, wr[1].x, acc1.x); acc1.y = fmaf(b0.y, wr[1].y, acc1.y);
        acc1.x = fmaf(b0.z, wr[2].x, acc1.x); acc1.y = fmaf(b0.z, wr[2].y, acc1.y);
        acc1.x = fmaf(b0.w, wr[3].x, acc1.x); acc1.y = fmaf(b0.w, wr[3].y, acc1.y);
        acc1.x = fmaf(b1.x, wr[4].x, acc1.x); acc1.y = fmaf(b1.x, wr[4].y, acc1.y);
        acc1.x = fmaf(b1.y, wr[5].x, acc1.x); acc1.y = fmaf(b1.y, wr[5].y, acc1.y);
        acc1.x = fmaf(b1.z, wr[6].x, acc1.x); acc1.y = fmaf(b1.z, wr[6].y, acc1.y);
        acc1.x = fmaf(b1.w, wr[7].x, acc1.x); acc1.y = fmaf(b1.w, wr[7].y, acc1.y);
    }
    *reinterpret_cast<float2*>(&qk[dst0][2 * j]) = acc0;
    *reinterpret_cast<float2*>(&qk[dst1][2 * j]) = acc1;
}

__global__ __launch_bounds__(512, 2)
void additive_local_attn(const float* __restrict__ x,
                         const float* __restrict__ Wt,
                         const float* __restrict__ Wx,
                         const float* __restrict__ Wa,
                         const float* __restrict__ bh,
                         const float* __restrict__ ba,
                         float* __restrict__ out)
{
    __shared__ __align__(16) float xs[XR_][D_];    // x rows i0-1 .. i0+7 (zero-padded)
    __shared__ __align__(16) float qk[NQK_][D_];   // 0..6: q[t], 7..15: k[r]
    __shared__ float sred[T_][2][3];               // per-query, per-warp-in-group partials

    const int tid  = threadIdx.x;
    const int grp  = tid >> 6;        // 0..7
    const int j    = tid & 63;        // channel pair index
    const int wig  = (tid >> 5) & 1;  // warp within group
    const int lane = tid & 31;
    const int b    = blockIdx.y;
    const int i0   = blockIdx.x * T_;

    const float* xb = x + (size_t)b * L_ * D_;

    // ---- stage x rows [i0-1, i0+7] ----
    for (int idx = tid; idx < XR_ * D_; idx += 512) {
        const int r = idx >> 7;
        const int c = idx & (D_ - 1);
        const int g = i0 - 1 + r;
        xs[r][c] = (g >= 0 && g < L_) ? xb[g * D_ + c] : 0.0f;
    }
    __syncthreads();

    // ---- phase 1: 16 row-GEMVs, 2 per group, each computed once ----
    // q[t] = xs[t+1] @ Wt -> qk[t]         (t = 0..6)
    // k[r] = xs[r]   @ Wx -> qk[7+r]       (r = 0..8)
    switch (grp) {
        case 0: gemv2<true >(xs, qk, Wt, 1, 0, Wt, 2, 1, j); break;
        case 1: gemv2<true >(xs, qk, Wt, 3, 2, Wt, 4, 3, j); break;
        case 2: gemv2<true >(xs, qk, Wt, 5, 4, Wt, 6, 5, j); break;
        case 3: gemv2<false>(xs, qk, Wt, 7, 6, Wx, 0, 7, j); break;   // q6 + k0
        case 4: gemv2<true >(xs, qk, Wx, 1, 8,  Wx, 2, 9,  j); break;
        case 5: gemv2<true >(xs, qk, Wx, 3, 10, Wx, 4, 11, j); break;
        case 6: gemv2<true >(xs, qk, Wx, 5, 12, Wx, 6, 13, j); break;
        default: gemv2<true>(xs, qk, Wx, 7, 14, Wx, 8, 15, j); break;
    }
    __syncthreads();

    // ---- phase 2: group t (<7) computes query t's 3 windowed logits ----
    if (grp < T_) {
        const int t = grp;
        const float2 wa2 = *reinterpret_cast<const float2*>(&Wa[2 * j]);
        const float2 bh2 = *reinterpret_cast<const float2*>(&bh[2 * j]);
        const float2 qv  = *reinterpret_cast<const float2*>(&qk[t][2 * j]);
        const float q0 = qv.x + bh2.x;
        const float q1 = qv.y + bh2.y;

        float p[3];
        #pragma unroll
        for (int jj = 0; jj < 3; ++jj) {
            const float2 kv = *reinterpret_cast<const float2*>(&qk[T_ + t + jj][2 * j]);
            p[jj] = wa2.x * tanh_approx(q0 + kv.x) + wa2.y * tanh_approx(q1 + kv.y);
        }
        #pragma unroll
        for (int off = 16; off; off >>= 1) {
            p[0] += __shfl_xor_sync(0xffffffffu, p[0], off);
            p[1] += __shfl_xor_sync(0xffffffffu, p[1], off);
            p[2] += __shfl_xor_sync(0xffffffffu, p[2], off);
        }
        if (lane == 0) {
            sred[t][wig][0] = p[0];
            sred[t][wig][1] = p[1];
            sred[t][wig][2] = p[2];
        }
    }
    __syncthreads();

    // ---- phase 3: windowed softmax (+EPS) + AV for query t = grp ----
    if (grp < T_) {
        const int t = grp;
        const int i = i0 + t;
        if (i < L_) {
            const float ba0 = ba[0];
            const float e0 = sred[t][0][0] + sred[t][1][0] + ba0;
            const float e1 = sred[t][0][1] + sred[t][1][1] + ba0;
            const float e2 = sred[t][0][2] + sred[t][1][2] + ba0;

            const bool v0 = (i - 1) >= 0;
            const bool v2 = (i + 1) < L_;

            float m = e1;
            if (v0) m = fmaxf(m, e0);
            if (v2) m = fmaxf(m, e2);

            const float w0 = v0 ? __expf(e0 - m) : 0.0f;
            const float w1 = __expf(e1 - m);
            const float w2 = v2 ? __expf(e2 - m) : 0.0f;
            const float inv = 1.0f / (w0 + w1 + w2 + EPS_);

            // x rows for query i are xs rows t, t+1, t+2
            const float2 xa = *reinterpret_cast<const float2*>(&xs[t][2 * j]);
            const float2 xm = *reinterpret_cast<const float2*>(&xs[t + 1][2 * j]);
            const float2 xc = *reinterpret_cast<const float2*>(&xs[t + 2][2 * j]);

            float2 o;
            o.x = (w0 * xa.x + w1 * xm.x + w2 * xc.x) * inv;
            o.y = (w0 * xa.y + w1 * xm.y + w2 * xc.y) * inv;
            *reinterpret_cast<float2*>(&out[((size_t)b * L_ + i) * D_ + 2 * j]) = o;
        }
    }
}

extern "C" void kernel_launch(void* const* d_in, const int* in_sizes, int n_in,
                              void* d_out, int out_size)
{
    const float* x  = (const float*)d_in[0];
    const float* Wt = (const float*)d_in[1];
    const float* Wx = (const float*)d_in[2];
    const float* Wa = (const float*)d_in[3];
    const float* bh = (const float*)d_in[4];
    const float* ba = (const float*)d_in[5];
    float* out = (float*)d_out;

    dim3 grid(TILES_, B_);   // 74 x 4 = 296 blocks = 148 SMs x 2 CTAs
    additive_local_attn<<<grid, 512>>>(x, Wt, Wx, Wa, bh, ba, out);
}